// round 2
// baseline (speedup 1.0000x reference)
#include <cuda_runtime.h>
#include <cuda_bf16.h>
#include <cstdint>

// Problem dims
#define BDIM 4096
#define NDIM 2048
#define KDIM 2048
#define DEPTH 7
#define WROWS 2049   // K rows + bias row

// Tiling
#define BLK_M 128
#define BLK_N 128
#define BLK_K 32

// SMEM layout (bf16 elements), padded strides for conflict-free ldmatrix
#define A_STRIDE 40            // 32 + 8 pad
#define B_STRIDE 136           // 128 + 8 pad
#define A_TILE (BLK_M * A_STRIDE)            // 5120 elems
#define B_TILE (BLK_K * B_STRIDE)            // 4352 elems
#define STAGE_ELEMS (2 * A_TILE + 2 * B_TILE)  // hi+lo for A and B = 18944
#define SMEM_BYTES (2 * STAGE_ELEMS * 2)       // double buffered = 75776 B

// Scratch (allocation-free rule: __device__ globals)
__device__ float g_act[2][(size_t)BDIM * NDIM];                       // ping-pong activations (fp32)
__device__ __nv_bfloat16 g_Whi[(size_t)DEPTH * WROWS * NDIM];         // weight hi split
__device__ __nv_bfloat16 g_Wlo[(size_t)DEPTH * WROWS * NDIM];         // weight lo split

// ---------------------------------------------------------------------------
// helpers
// ---------------------------------------------------------------------------
__device__ __forceinline__ void split2(float f0, float f1, uint32_t& hi, uint32_t& lo) {
    __nv_bfloat16 h0 = __float2bfloat16(f0);
    __nv_bfloat16 h1 = __float2bfloat16(f1);
    __nv_bfloat16 l0 = __float2bfloat16(f0 - __bfloat162float(h0));
    __nv_bfloat16 l1 = __float2bfloat16(f1 - __bfloat162float(h1));
    __nv_bfloat162 hp = __halves2bfloat162(h0, h1);
    __nv_bfloat162 lp = __halves2bfloat162(l0, l1);
    hi = *reinterpret_cast<uint32_t*>(&hp);
    lo = *reinterpret_cast<uint32_t*>(&lp);
}

__device__ __forceinline__ void ldsm4(uint32_t (&r)[4], const void* p) {
    uint32_t a = (uint32_t)__cvta_generic_to_shared(p);
    asm volatile("ldmatrix.sync.aligned.m8n8.x4.shared.b16 {%0,%1,%2,%3}, [%4];\n"
                 : "=r"(r[0]), "=r"(r[1]), "=r"(r[2]), "=r"(r[3]) : "r"(a));
}

__device__ __forceinline__ void ldsm4t(uint32_t (&r)[4], const void* p) {
    uint32_t a = (uint32_t)__cvta_generic_to_shared(p);
    asm volatile("ldmatrix.sync.aligned.m8n8.x4.trans.shared.b16 {%0,%1,%2,%3}, [%4];\n"
                 : "=r"(r[0]), "=r"(r[1]), "=r"(r[2]), "=r"(r[3]) : "r"(a));
}

__device__ __forceinline__ void mma_bf16(float (&d)[4], const uint32_t (&a)[4], const uint32_t* b) {
    asm volatile(
        "mma.sync.aligned.m16n8k16.row.col.f32.bf16.bf16.f32 "
        "{%0,%1,%2,%3}, {%4,%5,%6,%7}, {%8,%9}, {%0,%1,%2,%3};\n"
        : "+f"(d[0]), "+f"(d[1]), "+f"(d[2]), "+f"(d[3])
        : "r"(a[0]), "r"(a[1]), "r"(a[2]), "r"(a[3]), "r"(b[0]), "r"(b[1]));
}

// ---------------------------------------------------------------------------
// Weight split: fp32 W -> (hi, lo) bf16 pair, all 7 layers at once
// ---------------------------------------------------------------------------
__global__ void split_w_kernel(const float4* __restrict__ W, int n4) {
    int i = blockIdx.x * blockDim.x + threadIdx.x;
    if (i >= n4) return;
    float4 v = W[i];
    uint32_t h01, l01, h23, l23;
    split2(v.x, v.y, h01, l01);
    split2(v.z, v.w, h23, l23);
    uint2 uh; uh.x = h01; uh.y = h23;
    uint2 ul; ul.x = l01; ul.y = l23;
    reinterpret_cast<uint2*>(g_Whi)[i] = uh;
    reinterpret_cast<uint2*>(g_Wlo)[i] = ul;
}

// ---------------------------------------------------------------------------
// One masked-dense layer: C = relu(A @ W[0:2048,:] + W[2048,:])
// A: [4096,2048] fp32 (split to bf16x2 on the fly)
// W: pre-split bf16 hi/lo from g_Whi/g_Wlo (layer offset computed in-kernel)
// bf16x2 FMA: acc += ah*bh + ah*bl + al*bh   (rel err ~1e-5)
// ---------------------------------------------------------------------------
__global__ __launch_bounds__(256, 1)
void gemm_relu_kernel(const float* __restrict__ x_ext,
                      const float* __restrict__ Wfp_layer,   // fp32 layer base (bias row)
                      float* __restrict__ out_ext,
                      int layer, int in_sel, int out_sel)
{
    extern __shared__ __nv_bfloat16 smem[];

    const float* A = (in_sel == 0) ? x_ext : g_act[in_sel - 1];
    float* C = (out_sel == 0) ? out_ext : g_act[out_sel - 1];
    const __nv_bfloat16* WhiL = g_Whi + (size_t)layer * WROWS * NDIM;
    const __nv_bfloat16* WloL = g_Wlo + (size_t)layer * WROWS * NDIM;

    const int tid = threadIdx.x;
    const int lane = tid & 31;
    const int warp = tid >> 5;
    const int warp_m = warp >> 1;    // 0..3  (32 rows each)
    const int warp_n = warp & 1;     // 0..1  (64 cols each)
    const int bm = blockIdx.y;
    const int bn = blockIdx.x;

    // gmem load mapping
    const int a_row = tid >> 3;            // +p*32, p=0..3
    const int a_col = (tid & 7) * 4;       // 0..28
    const int b_row = tid >> 5;            // +p*8
    const int b_col = (tid & 31) * 4;      // 0..124

    const float* A_base = A + (size_t)(bm * BLK_M) * KDIM;

    float acc[2][8][4];
#pragma unroll
    for (int i = 0; i < 2; i++)
#pragma unroll
        for (int j = 0; j < 8; j++)
#pragma unroll
            for (int k = 0; k < 4; k++) acc[i][j][k] = 0.f;

    float4 a_reg[4];
    uint2 bh_reg[4], bl_reg[4];

    auto load_tile = [&](int ko) {
#pragma unroll
        for (int p = 0; p < 4; p++) {
            a_reg[p] = *reinterpret_cast<const float4*>(
                A_base + (size_t)(a_row + p * 32) * KDIM + ko * BLK_K + a_col);
            const size_t koff = (size_t)(ko * BLK_K + b_row + p * 8) * NDIM + bn * BLK_N + b_col;
            bh_reg[p] = *reinterpret_cast<const uint2*>(WhiL + koff);
            bl_reg[p] = *reinterpret_cast<const uint2*>(WloL + koff);
        }
    };

    auto store_tile = [&](int s) {
        __nv_bfloat16* Ah = smem + s * STAGE_ELEMS;
        __nv_bfloat16* Al = Ah + A_TILE;
        __nv_bfloat16* Bh = Al + A_TILE;
        __nv_bfloat16* Bl = Bh + B_TILE;
#pragma unroll
        for (int p = 0; p < 4; p++) {
            uint32_t h01, l01, h23, l23;
            split2(a_reg[p].x, a_reg[p].y, h01, l01);
            split2(a_reg[p].z, a_reg[p].w, h23, l23);
            uint2 uh; uh.x = h01; uh.y = h23;
            uint2 ul; ul.x = l01; ul.y = l23;
            const int ai = (a_row + p * 32) * A_STRIDE + a_col;
            *reinterpret_cast<uint2*>(Ah + ai) = uh;
            *reinterpret_cast<uint2*>(Al + ai) = ul;
            const int bi = (b_row + p * 8) * B_STRIDE + b_col;
            *reinterpret_cast<uint2*>(Bh + bi) = bh_reg[p];
            *reinterpret_cast<uint2*>(Bl + bi) = bl_reg[p];
        }
    };

    auto compute_stage = [&](int s) {
        const __nv_bfloat16* Ah = smem + s * STAGE_ELEMS;
        const __nv_bfloat16* Al = Ah + A_TILE;
        const __nv_bfloat16* Bh = Al + A_TILE;
        const __nv_bfloat16* Bl = Bh + B_TILE;
#pragma unroll
        for (int kk = 0; kk < 2; kk++) {
            uint32_t ah[2][4], al[2][4];
#pragma unroll
            for (int mi = 0; mi < 2; mi++) {
                const int aoff = (warp_m * 32 + mi * 16 + (lane & 15)) * A_STRIDE
                               + kk * 16 + ((lane >> 4) << 3);
                ldsm4(ah[mi], Ah + aoff);
                ldsm4(al[mi], Al + aoff);
            }
#pragma unroll
            for (int ng = 0; ng < 4; ng++) {
                uint32_t bh[4], bl[4];
                const int boff = (kk * 16 + (lane & 15)) * B_STRIDE
                               + warp_n * 64 + ng * 16 + ((lane >> 4) << 3);
                ldsm4t(bh, Bh + boff);
                ldsm4t(bl, Bl + boff);
#pragma unroll
                for (int mi = 0; mi < 2; mi++) {
#pragma unroll
                    for (int h = 0; h < 2; h++) {
                        float (&d)[4] = acc[mi][ng * 2 + h];
                        mma_bf16(d, ah[mi], &bh[h * 2]);
                        mma_bf16(d, ah[mi], &bl[h * 2]);
                        mma_bf16(d, al[mi], &bh[h * 2]);
                    }
                }
            }
        }
    };

    // ------ mainloop: double-buffered smem, register prefetch ------
    load_tile(0);
    store_tile(0);
    __syncthreads();
    const int KS = KDIM / BLK_K;   // 64
    for (int ko = 0; ko < KS; ko++) {
        const int s = ko & 1;
        if (ko + 1 < KS) load_tile(ko + 1);
        compute_stage(s);
        if (ko + 1 < KS) store_tile(s ^ 1);
        __syncthreads();
    }

    // ------ epilogue: bias (exact fp32 from W row 2048) + ReLU ------
    const float* bias = Wfp_layer + (size_t)(WROWS - 1) * NDIM;
    const int row0 = bm * BLK_M + warp_m * 32 + (lane >> 2);
    const int col0 = bn * BLK_N + warp_n * 64 + (lane & 3) * 2;
#pragma unroll
    for (int mi = 0; mi < 2; mi++) {
#pragma unroll
        for (int nn = 0; nn < 8; nn++) {
            const int c = col0 + nn * 8;
            const float b0 = __ldg(bias + c);
            const float b1 = __ldg(bias + c + 1);
            const int r = row0 + mi * 16;
            float2 v0, v1;
            v0.x = fmaxf(acc[mi][nn][0] + b0, 0.f);
            v0.y = fmaxf(acc[mi][nn][1] + b1, 0.f);
            v1.x = fmaxf(acc[mi][nn][2] + b0, 0.f);
            v1.y = fmaxf(acc[mi][nn][3] + b1, 0.f);
            *reinterpret_cast<float2*>(C + (size_t)r * NDIM + c) = v0;
            *reinterpret_cast<float2*>(C + (size_t)(r + 8) * NDIM + c) = v1;
        }
    }
}

// ---------------------------------------------------------------------------
// launch
// ---------------------------------------------------------------------------
extern "C" void kernel_launch(void* const* d_in, const int* in_sizes, int n_in,
                              void* d_out, int out_size) {
    (void)in_sizes; (void)n_in; (void)out_size;
    const float* x = (const float*)d_in[0];
    const float* W = (const float*)d_in[1];
    // d_in[2] (M) is provably redundant: W is already exactly masked.
    float* out = (float*)d_out;

    // 1) split weights into bf16 hi/lo (memory-bound, ~30us)
    const int n4 = DEPTH * WROWS * NDIM / 4;
    split_w_kernel<<<(n4 + 255) / 256, 256>>>((const float4*)W, n4);

    // 2) opt in to 75776 B dynamic smem (idempotent, host-side, capture-safe)
    cudaFuncSetAttribute(gemm_relu_kernel,
                         cudaFuncAttributeMaxDynamicSharedMemorySize, SMEM_BYTES);

    // 3) 7 chained GEMM+bias+ReLU layers, ping-pong activation buffers
    dim3 grid(NDIM / BLK_N, BDIM / BLK_M);   // (16, 32)
    for (int l = 0; l < DEPTH; l++) {
        const int in_sel  = (l == 0) ? 0 : 1 + ((l - 1) & 1);
        const int out_sel = (l == DEPTH - 1) ? 0 : 1 + (l & 1);
        gemm_relu_kernel<<<grid, 256, SMEM_BYTES>>>(
            x, W + (size_t)l * WROWS * NDIM, out, l, in_sel, out_sel);
    }
}

// round 4
// speedup vs baseline: 1.1429x; 1.1429x over previous
#include <cuda_runtime.h>
#include <cuda_bf16.h>
#include <cstdint>

// ---------------------------------------------------------------------------
// Problem dims
// ---------------------------------------------------------------------------
#define BDIM 4096
#define NDIM 2048
#define KDIM 2048
#define DEPTH 7
#define WROWS 2049            // K rows + bias row

// ---------------------------------------------------------------------------
// Tiling: 128x128 CTA tile, K-chunks of 32, 3-stage cp.async pipeline
// ---------------------------------------------------------------------------
#define BLK_M 128
#define BLK_N 128
#define BLK_K 32
#define CHUNKS (KDIM / BLK_K)     // 64
#define STAGES 3

#define A_STRIDE 40               // 32 + 8 pad (80 B rows, 16B-aligned, ldsm conflict-free)
#define B_STRIDE 136              // 128 + 8 pad (272 B rows)
#define A_TILE (BLK_M * A_STRIDE) // 5120 elems
#define B_TILE (BLK_K * B_STRIDE) // 4352 elems
#define STAGE_ELEMS (2 * A_TILE + 2 * B_TILE)   // hi+lo A, hi+lo B = 18944
#define STAGE_BYTES (STAGE_ELEMS * 2)           // 37888
#define SMEM_BYTES (STAGES * STAGE_BYTES)       // 113664  (2 CTAs/SM fit in 227KB)

// ---------------------------------------------------------------------------
// Device scratch (allocation-free rule)
// ---------------------------------------------------------------------------
__device__ __nv_bfloat16 g_xHi[(size_t)BDIM * NDIM];
__device__ __nv_bfloat16 g_xLo[(size_t)BDIM * NDIM];
__device__ __nv_bfloat16 g_aHi[2][(size_t)BDIM * NDIM];
__device__ __nv_bfloat16 g_aLo[2][(size_t)BDIM * NDIM];
__device__ __nv_bfloat16 g_Whi[(size_t)DEPTH * WROWS * NDIM];  // [l][k][n]
__device__ __nv_bfloat16 g_Wlo[(size_t)DEPTH * WROWS * NDIM];

// ---------------------------------------------------------------------------
// helpers
// ---------------------------------------------------------------------------
__device__ __forceinline__ void split2(float f0, float f1, uint32_t& hi, uint32_t& lo) {
    __nv_bfloat16 h0 = __float2bfloat16(f0);
    __nv_bfloat16 h1 = __float2bfloat16(f1);
    __nv_bfloat16 l0 = __float2bfloat16(f0 - __bfloat162float(h0));
    __nv_bfloat16 l1 = __float2bfloat16(f1 - __bfloat162float(h1));
    __nv_bfloat162 hp = __halves2bfloat162(h0, h1);
    __nv_bfloat162 lp = __halves2bfloat162(l0, l1);
    hi = *reinterpret_cast<uint32_t*>(&hp);
    lo = *reinterpret_cast<uint32_t*>(&lp);
}

__device__ __forceinline__ void ldsm4(uint32_t (&r)[4], const void* p) {
    uint32_t a = (uint32_t)__cvta_generic_to_shared(p);
    asm volatile("ldmatrix.sync.aligned.m8n8.x4.shared.b16 {%0,%1,%2,%3}, [%4];\n"
                 : "=r"(r[0]), "=r"(r[1]), "=r"(r[2]), "=r"(r[3]) : "r"(a));
}

__device__ __forceinline__ void ldsm4t(uint32_t (&r)[4], const void* p) {
    uint32_t a = (uint32_t)__cvta_generic_to_shared(p);
    asm volatile("ldmatrix.sync.aligned.m8n8.x4.trans.shared.b16 {%0,%1,%2,%3}, [%4];\n"
                 : "=r"(r[0]), "=r"(r[1]), "=r"(r[2]), "=r"(r[3]) : "r"(a));
}

__device__ __forceinline__ void mma_bf16(float (&d)[4], const uint32_t (&a)[4], const uint32_t* b) {
    asm volatile(
        "mma.sync.aligned.m16n8k16.row.col.f32.bf16.bf16.f32 "
        "{%0,%1,%2,%3}, {%4,%5,%6,%7}, {%8,%9}, {%0,%1,%2,%3};\n"
        : "+f"(d[0]), "+f"(d[1]), "+f"(d[2]), "+f"(d[3])
        : "r"(a[0]), "r"(a[1]), "r"(a[2]), "r"(a[3]), "r"(b[0]), "r"(b[1]));
}

__device__ __forceinline__ void cp16(uint32_t dst, const void* src) {
    asm volatile("cp.async.cg.shared.global [%0], [%1], 16;" :: "r"(dst), "l"(src));
}
#define CP_COMMIT() asm volatile("cp.async.commit_group;" ::: "memory")
#define CP_WAIT(n)  asm volatile("cp.async.wait_group %0;" :: "n"(n) : "memory")

// ---------------------------------------------------------------------------
// prep kernels
// ---------------------------------------------------------------------------
__global__ void wsplit_kernel(const float4* __restrict__ W, int n4) {
    int i = blockIdx.x * blockDim.x + threadIdx.x;
    if (i >= n4) return;
    float4 v = W[i];
    uint32_t h01, l01, h23, l23;
    split2(v.x, v.y, h01, l01);
    split2(v.z, v.w, h23, l23);
    uint2 uh; uh.x = h01; uh.y = h23;
    uint2 ul; ul.x = l01; ul.y = l23;
    reinterpret_cast<uint2*>(g_Whi)[i] = uh;
    reinterpret_cast<uint2*>(g_Wlo)[i] = ul;
}

__global__ void xsplit_kernel(const float4* __restrict__ x, int n4) {
    int i = blockIdx.x * blockDim.x + threadIdx.x;
    if (i >= n4) return;
    float4 v = x[i];
    uint32_t h01, l01, h23, l23;
    split2(v.x, v.y, h01, l01);
    split2(v.z, v.w, h23, l23);
    uint2 uh; uh.x = h01; uh.y = h23;
    uint2 ul; ul.x = l01; ul.y = l23;
    reinterpret_cast<uint2*>(g_xHi)[i] = uh;
    reinterpret_cast<uint2*>(g_xLo)[i] = ul;
}

// ---------------------------------------------------------------------------
// One layer: C = relu(A @ W + bias)
//   A, W pre-split bf16 hi/lo; 3 MMAs per K-step (ah*bh + ah*bl + al*bh).
//   cp.async 3-stage pipeline; epilogue splits activation for the next layer.
// ---------------------------------------------------------------------------
__global__ __launch_bounds__(256, 2)
void gemm_relu_kernel(const __nv_bfloat16* __restrict__ Ahi,
                      const __nv_bfloat16* __restrict__ Alo,
                      const __nv_bfloat16* __restrict__ Bhi,   // layer base [2049][2048]
                      const __nv_bfloat16* __restrict__ Blo,
                      const float* __restrict__ bias,          // fp32 W row 2048
                      float* __restrict__ outF,
                      __nv_bfloat16* __restrict__ nextHi,
                      __nv_bfloat16* __restrict__ nextLo,
                      int is_last)
{
    extern __shared__ __align__(128) __nv_bfloat16 smem[];
    const uint32_t sb = (uint32_t)__cvta_generic_to_shared(smem);

    const int tid = threadIdx.x;
    const int lane = tid & 31;
    const int warp = tid >> 5;
    const int warp_m = warp >> 1;   // 0..3 (32 rows each)
    const int warp_n = warp & 1;    // 0..1 (64 cols each)
    const int bm = blockIdx.y;
    const int bn = blockIdx.x;

    const __nv_bfloat16* A_base = Ahi + (size_t)(bm * BLK_M) * KDIM;
    const __nv_bfloat16* Al_base = Alo + (size_t)(bm * BLK_M) * KDIM;

    // cp.async mappings (8 x 16B per thread per stage)
    const int a_row = tid >> 1;              // 0..127
    const int a_c8  = (tid & 1) * 16;        // elem col 0 or 16 (two 16B chunks... see loop)
    const int b_row = tid >> 4;              // 0..15 (+16 in second pass)
    const int b_c8  = (tid & 15) * 8;        // elem col

    auto load_stage = [&](int s, int ko) {
        const uint32_t base = sb + s * STAGE_BYTES;
        // A: 128 rows x 32 cols; each thread: 1 row, 2 chunks of 8 elems
        {
            const size_t goff = (size_t)a_row * KDIM + ko * BLK_K + a_c8;
            const uint32_t soff = base + (a_row * A_STRIDE + a_c8) * 2;
            cp16(soff,      A_base + goff);
            cp16(soff + 16, A_base + goff + 8);
            cp16(soff + A_TILE * 2,      Al_base + goff);
            cp16(soff + A_TILE * 2 + 16, Al_base + goff + 8);
        }
        // B: 32 rows x 128 cols; each thread: 2 rows (b_row, b_row+16), 1 chunk each
        {
#pragma unroll
            for (int p = 0; p < 2; p++) {
                const int r = b_row + p * 16;
                const size_t goff = (size_t)(ko * BLK_K + r) * NDIM + bn * BLK_N + b_c8;
                const uint32_t soff = base + (2 * A_TILE + r * B_STRIDE + b_c8) * 2;
                cp16(soff, Bhi + goff);
                cp16(soff + B_TILE * 2, Blo + goff);
            }
        }
        CP_COMMIT();
    };

    float acc[2][8][4];
#pragma unroll
    for (int i = 0; i < 2; i++)
#pragma unroll
        for (int j = 0; j < 8; j++)
#pragma unroll
            for (int k = 0; k < 4; k++) acc[i][j][k] = 0.f;

    auto compute_stage = [&](int s) {
        const __nv_bfloat16* Ah = smem + s * STAGE_ELEMS;
        const __nv_bfloat16* Al = Ah + A_TILE;
        const __nv_bfloat16* Bh = Al + A_TILE;
        const __nv_bfloat16* Bl = Bh + B_TILE;
#pragma unroll
        for (int kk = 0; kk < 2; kk++) {
            uint32_t ah[2][4], al[2][4];
#pragma unroll
            for (int mi = 0; mi < 2; mi++) {
                const int aoff = (warp_m * 32 + mi * 16 + (lane & 15)) * A_STRIDE
                               + kk * 16 + ((lane >> 4) << 3);
                ldsm4(ah[mi], Ah + aoff);
                ldsm4(al[mi], Al + aoff);
            }
#pragma unroll
            for (int ng = 0; ng < 4; ng++) {
                uint32_t bh[4], bl[4];
                const int boff = (kk * 16 + (lane & 15)) * B_STRIDE
                               + warp_n * 64 + ng * 16 + ((lane >> 4) << 3);
                ldsm4t(bh, Bh + boff);
                ldsm4t(bl, Bl + boff);
#pragma unroll
                for (int mi = 0; mi < 2; mi++) {
#pragma unroll
                    for (int h = 0; h < 2; h++) {
                        float (&d)[4] = acc[mi][ng * 2 + h];
                        mma_bf16(d, ah[mi], &bh[h * 2]);
                        mma_bf16(d, ah[mi], &bl[h * 2]);
                        mma_bf16(d, al[mi], &bh[h * 2]);
                    }
                }
            }
        }
    };

    // ---------------- 3-stage pipeline ----------------
    load_stage(0, 0);
    load_stage(1, 1);
#pragma unroll 1
    for (int c = 0; c < CHUNKS; c++) {
        CP_WAIT(1);             // stage c's group complete
        __syncthreads();        // data visible to all; prior compute done -> (c-1)%3 free
        compute_stage(c % STAGES);
        if (c + 2 < CHUNKS) load_stage((c + 2) % STAGES, c + 2);
    }

    // ---------------- epilogue: bias + ReLU + split-store ----------------
    const int row0 = bm * BLK_M + warp_m * 32 + (lane >> 2);
    const int col0 = bn * BLK_N + warp_n * 64 + (lane & 3) * 2;
#pragma unroll
    for (int mi = 0; mi < 2; mi++) {
#pragma unroll
        for (int nn = 0; nn < 8; nn++) {
            const int c = col0 + nn * 8;
            const float b0 = __ldg(bias + c);
            const float b1 = __ldg(bias + c + 1);
            const int r = row0 + mi * 16;
            float v00 = fmaxf(acc[mi][nn][0] + b0, 0.f);
            float v01 = fmaxf(acc[mi][nn][1] + b1, 0.f);
            float v10 = fmaxf(acc[mi][nn][2] + b0, 0.f);
            float v11 = fmaxf(acc[mi][nn][3] + b1, 0.f);
            if (is_last) {
                float2 u0; u0.x = v00; u0.y = v01;
                float2 u1; u1.x = v10; u1.y = v11;
                *reinterpret_cast<float2*>(outF + (size_t)r * NDIM + c) = u0;
                *reinterpret_cast<float2*>(outF + (size_t)(r + 8) * NDIM + c) = u1;
            } else {
                uint32_t h0, l0, h1, l1;
                split2(v00, v01, h0, l0);
                split2(v10, v11, h1, l1);
                *reinterpret_cast<uint32_t*>(nextHi + (size_t)r * NDIM + c) = h0;
                *reinterpret_cast<uint32_t*>(nextLo + (size_t)r * NDIM + c) = l0;
                *reinterpret_cast<uint32_t*>(nextHi + (size_t)(r + 8) * NDIM + c) = h1;
                *reinterpret_cast<uint32_t*>(nextLo + (size_t)(r + 8) * NDIM + c) = l1;
            }
        }
    }
}

// ---------------------------------------------------------------------------
// launch
// ---------------------------------------------------------------------------
extern "C" void kernel_launch(void* const* d_in, const int* in_sizes, int n_in,
                              void* d_out, int out_size) {
    (void)in_sizes; (void)n_in; (void)out_size;
    const float* x = (const float*)d_in[0];
    const float* W = (const float*)d_in[1];
    float* out = (float*)d_out;

    void *pxh, *pxl, *pah, *pal, *pwh, *pwl;
    cudaGetSymbolAddress(&pxh, g_xHi);
    cudaGetSymbolAddress(&pxl, g_xLo);
    cudaGetSymbolAddress(&pah, g_aHi);
    cudaGetSymbolAddress(&pal, g_aLo);
    cudaGetSymbolAddress(&pwh, g_Whi);
    cudaGetSymbolAddress(&pwl, g_Wlo);
    __nv_bfloat16* xHi = (__nv_bfloat16*)pxh;
    __nv_bfloat16* xLo = (__nv_bfloat16*)pxl;
    __nv_bfloat16* aHi = (__nv_bfloat16*)pah;   // [2][B*N]
    __nv_bfloat16* aLo = (__nv_bfloat16*)pal;
    __nv_bfloat16* Whi = (__nv_bfloat16*)pwh;
    __nv_bfloat16* Wlo = (__nv_bfloat16*)pwl;
    const size_t ACT = (size_t)BDIM * NDIM;

    // 1) prep: split W (all layers) and x into bf16 hi/lo
    const int w4 = DEPTH * WROWS * NDIM / 4;
    wsplit_kernel<<<(w4 + 255) / 256, 256>>>((const float4*)W, w4);
    const int x4 = BDIM * NDIM / 4;
    xsplit_kernel<<<(x4 + 255) / 256, 256>>>((const float4*)x, x4);

    // 2) smem opt-in (113664 B -> 2 CTAs/SM)
    cudaFuncSetAttribute(gemm_relu_kernel,
                         cudaFuncAttributeMaxDynamicSharedMemorySize, SMEM_BYTES);

    // 3) 7 chained layers
    dim3 grid(NDIM / BLK_N, BDIM / BLK_M);   // (16, 32)
    for (int l = 0; l < DEPTH; l++) {
        const __nv_bfloat16* Ah = (l == 0) ? xHi : aHi + ((l - 1) & 1) * ACT;
        const __nv_bfloat16* Al = (l == 0) ? xLo : aLo + ((l - 1) & 1) * ACT;
        __nv_bfloat16* nH = aHi + (l & 1) * ACT;
        __nv_bfloat16* nL = aLo + (l & 1) * ACT;
        const size_t woff = (size_t)l * WROWS * NDIM;
        const float* bias = W + woff + (size_t)KDIM * NDIM;
        gemm_relu_kernel<<<grid, 256, SMEM_BYTES>>>(
            Ah, Al, Whi + woff, Wlo + woff, bias, out, nH, nL,
            (l == DEPTH - 1) ? 1 : 0);
    }
}

// round 5
// speedup vs baseline: 1.1431x; 1.0002x over previous
#include <cuda_runtime.h>
#include <cuda_bf16.h>
#include <cstdint>

// ---------------------------------------------------------------------------
// Problem dims
// ---------------------------------------------------------------------------
#define BDIM 4096
#define NDIM 2048
#define KDIM 2048
#define DEPTH 7
#define WROWS 2049            // K rows + bias row

// ---------------------------------------------------------------------------
// Tiling: 128x128 CTA tile, K-chunks of 32, 3-stage cp.async pipeline
// ---------------------------------------------------------------------------
#define BLK_M 128
#define BLK_N 128
#define BLK_K 32
#define CHUNKS (KDIM / BLK_K)     // 64
#define STAGES 3

#define A_STRIDE 40               // 32 + 8 pad
#define B_STRIDE 136              // 128 + 8 pad
#define A_TILE (BLK_M * A_STRIDE) // 5120 elems
#define B_TILE (BLK_K * B_STRIDE) // 4352 elems
#define STAGE_ELEMS (2 * A_TILE + 2 * B_TILE)   // 18944
#define STAGE_BYTES (STAGE_ELEMS * 2)           // 37888
#define SMEM_BYTES (STAGES * STAGE_BYTES)       // 113664 (2 CTAs/SM)

// ---------------------------------------------------------------------------
// Device scratch (allocation-free rule)
// ---------------------------------------------------------------------------
__device__ __nv_bfloat16 g_xHi[(size_t)BDIM * NDIM];
__device__ __nv_bfloat16 g_xLo[(size_t)BDIM * NDIM];
__device__ __nv_bfloat16 g_aHi[2][(size_t)BDIM * NDIM];
__device__ __nv_bfloat16 g_aLo[2][(size_t)BDIM * NDIM];
__device__ __nv_bfloat16 g_Whi[(size_t)DEPTH * WROWS * NDIM];  // [l][k][n]
__device__ __nv_bfloat16 g_Wlo[(size_t)DEPTH * WROWS * NDIM];

// ---------------------------------------------------------------------------
// helpers
// ---------------------------------------------------------------------------
__device__ __forceinline__ void split2(float f0, float f1, uint32_t& hi, uint32_t& lo) {
    __nv_bfloat16 h0 = __float2bfloat16(f0);
    __nv_bfloat16 h1 = __float2bfloat16(f1);
    __nv_bfloat16 l0 = __float2bfloat16(f0 - __bfloat162float(h0));
    __nv_bfloat16 l1 = __float2bfloat16(f1 - __bfloat162float(h1));
    __nv_bfloat162 hp = __halves2bfloat162(h0, h1);
    __nv_bfloat162 lp = __halves2bfloat162(l0, l1);
    hi = *reinterpret_cast<uint32_t*>(&hp);
    lo = *reinterpret_cast<uint32_t*>(&lp);
}

__device__ __forceinline__ void ldsm4(uint32_t (&r)[4], const void* p) {
    uint32_t a = (uint32_t)__cvta_generic_to_shared(p);
    asm volatile("ldmatrix.sync.aligned.m8n8.x4.shared.b16 {%0,%1,%2,%3}, [%4];\n"
                 : "=r"(r[0]), "=r"(r[1]), "=r"(r[2]), "=r"(r[3]) : "r"(a));
}

__device__ __forceinline__ void ldsm4t(uint32_t (&r)[4], const void* p) {
    uint32_t a = (uint32_t)__cvta_generic_to_shared(p);
    asm volatile("ldmatrix.sync.aligned.m8n8.x4.trans.shared.b16 {%0,%1,%2,%3}, [%4];\n"
                 : "=r"(r[0]), "=r"(r[1]), "=r"(r[2]), "=r"(r[3]) : "r"(a));
}

__device__ __forceinline__ void mma_bf16(float (&d)[4], const uint32_t (&a)[4], const uint32_t* b) {
    asm volatile(
        "mma.sync.aligned.m16n8k16.row.col.f32.bf16.bf16.f32 "
        "{%0,%1,%2,%3}, {%4,%5,%6,%7}, {%8,%9}, {%0,%1,%2,%3};\n"
        : "+f"(d[0]), "+f"(d[1]), "+f"(d[2]), "+f"(d[3])
        : "r"(a[0]), "r"(a[1]), "r"(a[2]), "r"(a[3]), "r"(b[0]), "r"(b[1]));
}

__device__ __forceinline__ void cp16(uint32_t dst, const void* src) {
    asm volatile("cp.async.cg.shared.global [%0], [%1], 16;" :: "r"(dst), "l"(src));
}
#define CP_COMMIT() asm volatile("cp.async.commit_group;" ::: "memory")
#define CP_WAIT(n)  asm volatile("cp.async.wait_group %0;" :: "n"(n) : "memory")

// ---------------------------------------------------------------------------
// prep kernels
// ---------------------------------------------------------------------------
__global__ void wsplit_kernel(const float4* __restrict__ W, int n4) {
    int i = blockIdx.x * blockDim.x + threadIdx.x;
    if (i >= n4) return;
    float4 v = W[i];
    uint32_t h01, l01, h23, l23;
    split2(v.x, v.y, h01, l01);
    split2(v.z, v.w, h23, l23);
    uint2 uh; uh.x = h01; uh.y = h23;
    uint2 ul; ul.x = l01; ul.y = l23;
    reinterpret_cast<uint2*>(g_Whi)[i] = uh;
    reinterpret_cast<uint2*>(g_Wlo)[i] = ul;
}

__global__ void xsplit_kernel(const float4* __restrict__ x, int n4) {
    int i = blockIdx.x * blockDim.x + threadIdx.x;
    if (i >= n4) return;
    float4 v = x[i];
    uint32_t h01, l01, h23, l23;
    split2(v.x, v.y, h01, l01);
    split2(v.z, v.w, h23, l23);
    uint2 uh; uh.x = h01; uh.y = h23;
    uint2 ul; ul.x = l01; ul.y = l23;
    reinterpret_cast<uint2*>(g_xHi)[i] = uh;
    reinterpret_cast<uint2*>(g_xLo)[i] = ul;
}

// ---------------------------------------------------------------------------
// One layer: C = relu(A @ W + bias)
//   A, W pre-split bf16 hi/lo; 3 MMAs per K-step (ah*bh + ah*bl + al*bh),
//   issued in term-groups of 8 independent MMAs to break RAW chains.
// ---------------------------------------------------------------------------
__global__ __launch_bounds__(256, 2)
void gemm_relu_kernel(const __nv_bfloat16* __restrict__ Ahi,
                      const __nv_bfloat16* __restrict__ Alo,
                      const __nv_bfloat16* __restrict__ Bhi,
                      const __nv_bfloat16* __restrict__ Blo,
                      const float* __restrict__ bias,
                      float* __restrict__ outF,
                      __nv_bfloat16* __restrict__ nextHi,
                      __nv_bfloat16* __restrict__ nextLo,
                      int is_last)
{
    extern __shared__ __align__(128) __nv_bfloat16 smem[];
    const uint32_t sb = (uint32_t)__cvta_generic_to_shared(smem);

    const int tid = threadIdx.x;
    const int lane = tid & 31;
    const int warp = tid >> 5;
    const int warp_m = warp >> 1;   // 0..3 (32 rows each)
    const int warp_n = warp & 1;    // 0..1 (64 cols each)
    const int bm = blockIdx.y;
    const int bn = blockIdx.x;

    const __nv_bfloat16* A_base = Ahi + (size_t)(bm * BLK_M) * KDIM;
    const __nv_bfloat16* Al_base = Alo + (size_t)(bm * BLK_M) * KDIM;

    const int a_row = tid >> 1;
    const int a_c8  = (tid & 1) * 16;
    const int b_row = tid >> 4;
    const int b_c8  = (tid & 15) * 8;

    auto load_stage = [&](int s, int ko) {
        const uint32_t base = sb + s * STAGE_BYTES;
        {
            const size_t goff = (size_t)a_row * KDIM + ko * BLK_K + a_c8;
            const uint32_t soff = base + (a_row * A_STRIDE + a_c8) * 2;
            cp16(soff,      A_base + goff);
            cp16(soff + 16, A_base + goff + 8);
            cp16(soff + A_TILE * 2,      Al_base + goff);
            cp16(soff + A_TILE * 2 + 16, Al_base + goff + 8);
        }
        {
#pragma unroll
            for (int p = 0; p < 2; p++) {
                const int r = b_row + p * 16;
                const size_t goff = (size_t)(ko * BLK_K + r) * NDIM + bn * BLK_N + b_c8;
                const uint32_t soff = base + (2 * A_TILE + r * B_STRIDE + b_c8) * 2;
                cp16(soff, Bhi + goff);
                cp16(soff + B_TILE * 2, Blo + goff);
            }
        }
        CP_COMMIT();
    };

    float acc[2][8][4];
#pragma unroll
    for (int i = 0; i < 2; i++)
#pragma unroll
        for (int j = 0; j < 8; j++)
#pragma unroll
            for (int k = 0; k < 4; k++) acc[i][j][k] = 0.f;

    auto compute_stage = [&](int s) {
        const __nv_bfloat16* Ah = smem + s * STAGE_ELEMS;
        const __nv_bfloat16* Al = Ah + A_TILE;
        const __nv_bfloat16* Bh = Al + A_TILE;
        const __nv_bfloat16* Bl = Bh + B_TILE;
#pragma unroll
        for (int kk = 0; kk < 2; kk++) {
            // A fragments for this k-slice (hi and lo), all mi at once
            uint32_t ah[2][4], al[2][4];
#pragma unroll
            for (int mi = 0; mi < 2; mi++) {
                const int aoff = (warp_m * 32 + mi * 16 + (lane & 15)) * A_STRIDE
                               + kk * 16 + ((lane >> 4) << 3);
                ldsm4(ah[mi], Ah + aoff);
                ldsm4(al[mi], Al + aoff);
            }
            // B in ng-pairs; per pair: 3 term-groups of 8 independent MMAs
#pragma unroll
            for (int ngp = 0; ngp < 2; ngp++) {
                uint32_t bh[2][4], bl[2][4];
#pragma unroll
                for (int j = 0; j < 2; j++) {
                    const int ng = ngp * 2 + j;
                    const int boff = (kk * 16 + (lane & 15)) * B_STRIDE
                                   + warp_n * 64 + ng * 16 + ((lane >> 4) << 3);
                    ldsm4t(bh[j], Bh + boff);
                    ldsm4t(bl[j], Bl + boff);
                }
                // term 1: ah * bh  (8 independent accumulators)
#pragma unroll
                for (int j = 0; j < 2; j++)
#pragma unroll
                    for (int mi = 0; mi < 2; mi++)
#pragma unroll
                        for (int h = 0; h < 2; h++)
                            mma_bf16(acc[mi][(ngp * 2 + j) * 2 + h], ah[mi], &bh[j][h * 2]);
                // term 2: ah * bl
#pragma unroll
                for (int j = 0; j < 2; j++)
#pragma unroll
                    for (int mi = 0; mi < 2; mi++)
#pragma unroll
                        for (int h = 0; h < 2; h++)
                            mma_bf16(acc[mi][(ngp * 2 + j) * 2 + h], ah[mi], &bl[j][h * 2]);
                // term 3: al * bh
#pragma unroll
                for (int j = 0; j < 2; j++)
#pragma unroll
                    for (int mi = 0; mi < 2; mi++)
#pragma unroll
                        for (int h = 0; h < 2; h++)
                            mma_bf16(acc[mi][(ngp * 2 + j) * 2 + h], al[mi], &bh[j][h * 2]);
            }
        }
    };

    // ---------------- 3-stage pipeline ----------------
    load_stage(0, 0);
    load_stage(1, 1);
#pragma unroll 1
    for (int c = 0; c < CHUNKS; c++) {
        CP_WAIT(1);
        __syncthreads();
        compute_stage(c % STAGES);
        if (c + 2 < CHUNKS) load_stage((c + 2) % STAGES, c + 2);
    }

    // ---------------- epilogue: bias + ReLU + split-store ----------------
    const int row0 = bm * BLK_M + warp_m * 32 + (lane >> 2);
    const int col0 = bn * BLK_N + warp_n * 64 + (lane & 3) * 2;
#pragma unroll
    for (int mi = 0; mi < 2; mi++) {
#pragma unroll
        for (int nn = 0; nn < 8; nn++) {
            const int c = col0 + nn * 8;
            const float b0 = __ldg(bias + c);
            const float b1 = __ldg(bias + c + 1);
            const int r = row0 + mi * 16;
            float v00 = fmaxf(acc[mi][nn][0] + b0, 0.f);
            float v01 = fmaxf(acc[mi][nn][1] + b1, 0.f);
            float v10 = fmaxf(acc[mi][nn][2] + b0, 0.f);
            float v11 = fmaxf(acc[mi][nn][3] + b1, 0.f);
            if (is_last) {
                float2 u0; u0.x = v00; u0.y = v01;
                float2 u1; u1.x = v10; u1.y = v11;
                *reinterpret_cast<float2*>(outF + (size_t)r * NDIM + c) = u0;
                *reinterpret_cast<float2*>(outF + (size_t)(r + 8) * NDIM + c) = u1;
            } else {
                uint32_t h0, l0, h1, l1;
                split2(v00, v01, h0, l0);
                split2(v10, v11, h1, l1);
                *reinterpret_cast<uint32_t*>(nextHi + (size_t)r * NDIM + c) = h0;
                *reinterpret_cast<uint32_t*>(nextLo + (size_t)r * NDIM + c) = l0;
                *reinterpret_cast<uint32_t*>(nextHi + (size_t)(r + 8) * NDIM + c) = h1;
                *reinterpret_cast<uint32_t*>(nextLo + (size_t)(r + 8) * NDIM + c) = l1;
            }
        }
    }
}

// ---------------------------------------------------------------------------
// launch
// ---------------------------------------------------------------------------
extern "C" void kernel_launch(void* const* d_in, const int* in_sizes, int n_in,
                              void* d_out, int out_size) {
    (void)in_sizes; (void)n_in; (void)out_size;
    const float* x = (const float*)d_in[0];
    const float* W = (const float*)d_in[1];
    float* out = (float*)d_out;

    void *pxh, *pxl, *pah, *pal, *pwh, *pwl;
    cudaGetSymbolAddress(&pxh, g_xHi);
    cudaGetSymbolAddress(&pxl, g_xLo);
    cudaGetSymbolAddress(&pah, g_aHi);
    cudaGetSymbolAddress(&pal, g_aLo);
    cudaGetSymbolAddress(&pwh, g_Whi);
    cudaGetSymbolAddress(&pwl, g_Wlo);
    __nv_bfloat16* xHi = (__nv_bfloat16*)pxh;
    __nv_bfloat16* xLo = (__nv_bfloat16*)pxl;
    __nv_bfloat16* aHi = (__nv_bfloat16*)pah;
    __nv_bfloat16* aLo = (__nv_bfloat16*)pal;
    __nv_bfloat16* Whi = (__nv_bfloat16*)pwh;
    __nv_bfloat16* Wlo = (__nv_bfloat16*)pwl;
    const size_t ACT = (size_t)BDIM * NDIM;

    const int w4 = DEPTH * WROWS * NDIM / 4;
    wsplit_kernel<<<(w4 + 255) / 256, 256>>>((const float4*)W, w4);
    const int x4 = BDIM * NDIM / 4;
    xsplit_kernel<<<(x4 + 255) / 256, 256>>>((const float4*)x, x4);

    cudaFuncSetAttribute(gemm_relu_kernel,
                         cudaFuncAttributeMaxDynamicSharedMemorySize, SMEM_BYTES);

    dim3 grid(NDIM / BLK_N, BDIM / BLK_M);   // (16, 32)
    for (int l = 0; l < DEPTH; l++) {
        const __nv_bfloat16* Ah = (l == 0) ? xHi : aHi + ((l - 1) & 1) * ACT;
        const __nv_bfloat16* Al = (l == 0) ? xLo : aLo + ((l - 1) & 1) * ACT;
        __nv_bfloat16* nH = aHi + (l & 1) * ACT;
        __nv_bfloat16* nL = aLo + (l & 1) * ACT;
        const size_t woff = (size_t)l * WROWS * NDIM;
        const float* bias = W + woff + (size_t)KDIM * NDIM;
        gemm_relu_kernel<<<grid, 256, SMEM_BYTES>>>(
            Ah, Al, Whi + woff, Wlo + woff, bias, out, nH, nL,
            (l == DEPTH - 1) ? 1 : 0);
    }
}

// round 6
// speedup vs baseline: 1.6109x; 1.4092x over previous
#include <cuda_runtime.h>
#include <cuda_fp16.h>
#include <cstdint>

// ---------------------------------------------------------------------------
// Problem dims
// ---------------------------------------------------------------------------
#define BDIM 4096
#define NDIM 2048
#define KDIM 2048
#define DEPTH 7
#define WROWS 2049            // K rows + bias row

// ---------------------------------------------------------------------------
// Tiling: 128x128 CTA tile, K-chunks of 32, 4-stage cp.async pipeline
// ---------------------------------------------------------------------------
#define BLK_M 128
#define BLK_N 128
#define BLK_K 32
#define CHUNKS (KDIM / BLK_K)     // 64
#define STAGES 4

#define A_STRIDE 40               // 32 + 8 pad
#define B_STRIDE 136              // 128 + 8 pad
#define A_TILE (BLK_M * A_STRIDE) // 5120 elems (fp16, hi only)
#define B_TILE (BLK_K * B_STRIDE) // 4352 elems
#define STAGE_ELEMS (A_TILE + 2 * B_TILE)       // A + B hi + B lo = 13824
#define STAGE_BYTES (STAGE_ELEMS * 2)           // 27648
#define SMEM_BYTES (STAGES * STAGE_BYTES)       // 110592 (2 CTAs/SM)

// ---------------------------------------------------------------------------
// Device scratch (allocation-free rule)
// ---------------------------------------------------------------------------
__device__ __half g_xH[(size_t)BDIM * NDIM];                  // input, fp16
__device__ __half g_a[2][(size_t)BDIM * NDIM];                // ping-pong activations, fp16
__device__ __half g_Whi[(size_t)DEPTH * WROWS * NDIM];        // weight hi
__device__ __half g_Wlo[(size_t)DEPTH * WROWS * NDIM];        // weight lo (exact residual)

// ---------------------------------------------------------------------------
// helpers
// ---------------------------------------------------------------------------
__device__ __forceinline__ void ldsm4(uint32_t (&r)[4], const void* p) {
    uint32_t a = (uint32_t)__cvta_generic_to_shared(p);
    asm volatile("ldmatrix.sync.aligned.m8n8.x4.shared.b16 {%0,%1,%2,%3}, [%4];\n"
                 : "=r"(r[0]), "=r"(r[1]), "=r"(r[2]), "=r"(r[3]) : "r"(a));
}

__device__ __forceinline__ void ldsm4t(uint32_t (&r)[4], const void* p) {
    uint32_t a = (uint32_t)__cvta_generic_to_shared(p);
    asm volatile("ldmatrix.sync.aligned.m8n8.x4.trans.shared.b16 {%0,%1,%2,%3}, [%4];\n"
                 : "=r"(r[0]), "=r"(r[1]), "=r"(r[2]), "=r"(r[3]) : "r"(a));
}

__device__ __forceinline__ void mma_f16(float (&d)[4], const uint32_t (&a)[4], const uint32_t* b) {
    asm volatile(
        "mma.sync.aligned.m16n8k16.row.col.f32.f16.f16.f32 "
        "{%0,%1,%2,%3}, {%4,%5,%6,%7}, {%8,%9}, {%0,%1,%2,%3};\n"
        : "+f"(d[0]), "+f"(d[1]), "+f"(d[2]), "+f"(d[3])
        : "r"(a[0]), "r"(a[1]), "r"(a[2]), "r"(a[3]), "r"(b[0]), "r"(b[1]));
}

__device__ __forceinline__ void cp16(uint32_t dst, const void* src) {
    asm volatile("cp.async.cg.shared.global [%0], [%1], 16;" :: "r"(dst), "l"(src));
}
#define CP_COMMIT() asm volatile("cp.async.commit_group;" ::: "memory")
#define CP_WAIT(n)  asm volatile("cp.async.wait_group %0;" :: "n"(n) : "memory")

// ---------------------------------------------------------------------------
// prep kernels
// ---------------------------------------------------------------------------
// W fp32 -> fp16 hi + exact fp16 residual lo
__global__ void wsplit_kernel(const float4* __restrict__ W, int n4) {
    int i = blockIdx.x * blockDim.x + threadIdx.x;
    if (i >= n4) return;
    float4 v = W[i];
    __half h0 = __float2half_rn(v.x), h1 = __float2half_rn(v.y);
    __half h2 = __float2half_rn(v.z), h3 = __float2half_rn(v.w);
    __half l0 = __float2half_rn(v.x - __half2float(h0));
    __half l1 = __float2half_rn(v.y - __half2float(h1));
    __half l2 = __float2half_rn(v.z - __half2float(h2));
    __half l3 = __float2half_rn(v.w - __half2float(h3));
    __half2 H0 = __halves2half2(h0, h1), H1 = __halves2half2(h2, h3);
    __half2 L0 = __halves2half2(l0, l1), L1 = __halves2half2(l2, l3);
    uint2 uh; uh.x = *(uint32_t*)&H0; uh.y = *(uint32_t*)&H1;
    uint2 ul; ul.x = *(uint32_t*)&L0; ul.y = *(uint32_t*)&L1;
    reinterpret_cast<uint2*>(g_Whi)[i] = uh;
    reinterpret_cast<uint2*>(g_Wlo)[i] = ul;
}

// x fp32 -> fp16
__global__ void xcvt_kernel(const float4* __restrict__ x, int n4) {
    int i = blockIdx.x * blockDim.x + threadIdx.x;
    if (i >= n4) return;
    float4 v = x[i];
    __half2 H0 = __floats2half2_rn(v.x, v.y);
    __half2 H1 = __floats2half2_rn(v.z, v.w);
    uint2 u; u.x = *(uint32_t*)&H0; u.y = *(uint32_t*)&H1;
    reinterpret_cast<uint2*>(g_xH)[i] = u;
}

// ---------------------------------------------------------------------------
// One layer: C = relu(A @ (Wh + Wl) + bias)
//   A fp16 (single), W fp16 hi/lo; 2 MMAs per K-step.
// ---------------------------------------------------------------------------
__global__ __launch_bounds__(256, 2)
void gemm_relu_kernel(const __half* __restrict__ A,
                      const __half* __restrict__ Bhi,
                      const __half* __restrict__ Blo,
                      const float* __restrict__ bias,
                      float* __restrict__ outF,
                      __half* __restrict__ nextA,
                      int is_last)
{
    extern __shared__ __align__(128) __half smem[];
    const uint32_t sb = (uint32_t)__cvta_generic_to_shared(smem);

    const int tid = threadIdx.x;
    const int lane = tid & 31;
    const int warp = tid >> 5;
    const int warp_m = warp >> 1;   // 0..3 (32 rows each)
    const int warp_n = warp & 1;    // 0..1 (64 cols each)
    const int bm = blockIdx.y;
    const int bn = blockIdx.x;

    const __half* A_base = A + (size_t)(bm * BLK_M) * KDIM;

    const int a_row = tid >> 1;              // 0..127
    const int a_c8  = (tid & 1) * 16;        // 0 or 16
    const int b_row = tid >> 4;              // 0..15 (+16)
    const int b_c8  = (tid & 15) * 8;

    auto load_stage = [&](int s, int ko) {
        const uint32_t base = sb + s * STAGE_BYTES;
        {
            const size_t goff = (size_t)a_row * KDIM + ko * BLK_K + a_c8;
            const uint32_t soff = base + (a_row * A_STRIDE + a_c8) * 2;
            cp16(soff,      A_base + goff);
            cp16(soff + 16, A_base + goff + 8);
        }
        {
#pragma unroll
            for (int p = 0; p < 2; p++) {
                const int r = b_row + p * 16;
                const size_t goff = (size_t)(ko * BLK_K + r) * NDIM + bn * BLK_N + b_c8;
                const uint32_t soff = base + (A_TILE + r * B_STRIDE + b_c8) * 2;
                cp16(soff, Bhi + goff);
                cp16(soff + B_TILE * 2, Blo + goff);
            }
        }
        CP_COMMIT();
    };

    float acc[2][8][4];
#pragma unroll
    for (int i = 0; i < 2; i++)
#pragma unroll
        for (int j = 0; j < 8; j++)
#pragma unroll
            for (int k = 0; k < 4; k++) acc[i][j][k] = 0.f;

    auto compute_stage = [&](int s) {
        const __half* Ah = smem + s * STAGE_ELEMS;
        const __half* Bh = Ah + A_TILE;
        const __half* Bl = Bh + B_TILE;
#pragma unroll
        for (int kk = 0; kk < 2; kk++) {
            uint32_t ah[2][4];
#pragma unroll
            for (int mi = 0; mi < 2; mi++) {
                const int aoff = (warp_m * 32 + mi * 16 + (lane & 15)) * A_STRIDE
                               + kk * 16 + ((lane >> 4) << 3);
                ldsm4(ah[mi], Ah + aoff);
            }
#pragma unroll
            for (int ng = 0; ng < 4; ng++) {
                uint32_t bh[4], bl[4];
                const int boff = (kk * 16 + (lane & 15)) * B_STRIDE
                               + warp_n * 64 + ng * 16 + ((lane >> 4) << 3);
                ldsm4t(bh, Bh + boff);
                ldsm4t(bl, Bl + boff);
#pragma unroll
                for (int mi = 0; mi < 2; mi++) {
#pragma unroll
                    for (int h = 0; h < 2; h++) {
                        float (&d)[4] = acc[mi][ng * 2 + h];
                        mma_f16(d, ah[mi], &bh[h * 2]);
                        mma_f16(d, ah[mi], &bl[h * 2]);
                    }
                }
            }
        }
    };

    // ---------------- 4-stage pipeline ----------------
    load_stage(0, 0);
    load_stage(1, 1);
    load_stage(2, 2);
#pragma unroll 1
    for (int c = 0; c < CHUNKS; c++) {
        CP_WAIT(2);
        __syncthreads();
        compute_stage(c & 3);
        if (c + 3 < CHUNKS) load_stage((c + 3) & 3, c + 3);
    }

    // ---------------- epilogue: bias + ReLU + store ----------------
    const int row0 = bm * BLK_M + warp_m * 32 + (lane >> 2);
    const int col0 = bn * BLK_N + warp_n * 64 + (lane & 3) * 2;
#pragma unroll
    for (int mi = 0; mi < 2; mi++) {
#pragma unroll
        for (int nn = 0; nn < 8; nn++) {
            const int c = col0 + nn * 8;
            const float b0 = __ldg(bias + c);
            const float b1 = __ldg(bias + c + 1);
            const int r = row0 + mi * 16;
            float v00 = fmaxf(acc[mi][nn][0] + b0, 0.f);
            float v01 = fmaxf(acc[mi][nn][1] + b1, 0.f);
            float v10 = fmaxf(acc[mi][nn][2] + b0, 0.f);
            float v11 = fmaxf(acc[mi][nn][3] + b1, 0.f);
            if (is_last) {
                float2 u0; u0.x = v00; u0.y = v01;
                float2 u1; u1.x = v10; u1.y = v11;
                *reinterpret_cast<float2*>(outF + (size_t)r * NDIM + c) = u0;
                *reinterpret_cast<float2*>(outF + (size_t)(r + 8) * NDIM + c) = u1;
            } else {
                __half2 h0 = __floats2half2_rn(v00, v01);
                __half2 h1 = __floats2half2_rn(v10, v11);
                *reinterpret_cast<__half2*>(nextA + (size_t)r * NDIM + c) = h0;
                *reinterpret_cast<__half2*>(nextA + (size_t)(r + 8) * NDIM + c) = h1;
            }
        }
    }
}

// ---------------------------------------------------------------------------
// launch
// ---------------------------------------------------------------------------
extern "C" void kernel_launch(void* const* d_in, const int* in_sizes, int n_in,
                              void* d_out, int out_size) {
    (void)in_sizes; (void)n_in; (void)out_size;
    const float* x = (const float*)d_in[0];
    const float* W = (const float*)d_in[1];
    float* out = (float*)d_out;

    void *pxh, *pa, *pwh, *pwl;
    cudaGetSymbolAddress(&pxh, g_xH);
    cudaGetSymbolAddress(&pa, g_a);
    cudaGetSymbolAddress(&pwh, g_Whi);
    cudaGetSymbolAddress(&pwl, g_Wlo);
    __half* xH  = (__half*)pxh;
    __half* aP  = (__half*)pa;     // [2][B*N]
    __half* Whi = (__half*)pwh;
    __half* Wlo = (__half*)pwl;
    const size_t ACT = (size_t)BDIM * NDIM;

    const int w4 = DEPTH * WROWS * NDIM / 4;
    wsplit_kernel<<<(w4 + 255) / 256, 256>>>((const float4*)W, w4);
    const int x4 = BDIM * NDIM / 4;
    xcvt_kernel<<<(x4 + 255) / 256, 256>>>((const float4*)x, x4);

    cudaFuncSetAttribute(gemm_relu_kernel,
                         cudaFuncAttributeMaxDynamicSharedMemorySize, SMEM_BYTES);

    dim3 grid(NDIM / BLK_N, BDIM / BLK_M);   // (16, 32)
    for (int l = 0; l < DEPTH; l++) {
        const __half* Al = (l == 0) ? xH : aP + ((l - 1) & 1) * ACT;
        __half* nA = aP + (l & 1) * ACT;
        const size_t woff = (size_t)l * WROWS * NDIM;
        const float* bias = W + woff + (size_t)KDIM * NDIM;
        gemm_relu_kernel<<<grid, 256, SMEM_BYTES>>>(
            Al, Whi + woff, Wlo + woff, bias, out, nA,
            (l == DEPTH - 1) ? 1 : 0);
    }
}

// round 7
// speedup vs baseline: 2.5121x; 1.5594x over previous
#include <cuda_runtime.h>
#include <cuda_fp16.h>
#include <cstdint>

// ---------------------------------------------------------------------------
// Problem dims
// ---------------------------------------------------------------------------
#define BDIM 4096
#define NDIM 2048
#define KDIM 2048
#define DEPTH 7
#define WROWS 2049            // K rows + bias row

// ---------------------------------------------------------------------------
// Tiling: 128x128 CTA tile, K-chunks of 64, 3-stage cp.async pipeline
// ---------------------------------------------------------------------------
#define BLK_M 128
#define BLK_N 128
#define BLK_K 64
#define CHUNKS (KDIM / BLK_K)     // 32
#define STAGES 3

#define A_STRIDE 72               // 64 + 8 pad (144 B rows -> 16B drift/row, ldsm conflict-free)
#define B_STRIDE 136              // 128 + 8 pad (272 B rows)
#define A_TILE (BLK_M * A_STRIDE) // 9216 elems
#define B_TILE (BLK_K * B_STRIDE) // 8704 elems
#define STAGE_ELEMS (A_TILE + B_TILE)           // 17920
#define STAGE_BYTES (STAGE_ELEMS * 2)           // 35840
#define SMEM_BYTES (STAGES * STAGE_BYTES)       // 107520 (2 CTAs/SM in 227KB)

// ---------------------------------------------------------------------------
// Device scratch (allocation-free rule)
// ---------------------------------------------------------------------------
__device__ __half g_xH[(size_t)BDIM * NDIM];              // input, fp16
__device__ __half g_a[2][(size_t)BDIM * NDIM];            // ping-pong activations, fp16
__device__ __half g_Wh[(size_t)DEPTH * WROWS * NDIM];     // weights, fp16

// ---------------------------------------------------------------------------
// helpers
// ---------------------------------------------------------------------------
__device__ __forceinline__ void ldsm4(uint32_t (&r)[4], const void* p) {
    uint32_t a = (uint32_t)__cvta_generic_to_shared(p);
    asm volatile("ldmatrix.sync.aligned.m8n8.x4.shared.b16 {%0,%1,%2,%3}, [%4];\n"
                 : "=r"(r[0]), "=r"(r[1]), "=r"(r[2]), "=r"(r[3]) : "r"(a));
}

__device__ __forceinline__ void ldsm4t(uint32_t (&r)[4], const void* p) {
    uint32_t a = (uint32_t)__cvta_generic_to_shared(p);
    asm volatile("ldmatrix.sync.aligned.m8n8.x4.trans.shared.b16 {%0,%1,%2,%3}, [%4];\n"
                 : "=r"(r[0]), "=r"(r[1]), "=r"(r[2]), "=r"(r[3]) : "r"(a));
}

__device__ __forceinline__ void mma_f16(float (&d)[4], const uint32_t (&a)[4], const uint32_t* b) {
    asm volatile(
        "mma.sync.aligned.m16n8k16.row.col.f32.f16.f16.f32 "
        "{%0,%1,%2,%3}, {%4,%5,%6,%7}, {%8,%9}, {%0,%1,%2,%3};\n"
        : "+f"(d[0]), "+f"(d[1]), "+f"(d[2]), "+f"(d[3])
        : "r"(a[0]), "r"(a[1]), "r"(a[2]), "r"(a[3]), "r"(b[0]), "r"(b[1]));
}

__device__ __forceinline__ void cp16(uint32_t dst, const void* src) {
    asm volatile("cp.async.cg.shared.global [%0], [%1], 16;" :: "r"(dst), "l"(src));
}
#define CP_COMMIT() asm volatile("cp.async.commit_group;" ::: "memory")
#define CP_WAIT(n)  asm volatile("cp.async.wait_group %0;" :: "n"(n) : "memory")

// ---------------------------------------------------------------------------
// prep kernels: fp32 -> fp16
// ---------------------------------------------------------------------------
__global__ void wcvt_kernel(const float4* __restrict__ W, int n4) {
    int i = blockIdx.x * blockDim.x + threadIdx.x;
    if (i >= n4) return;
    float4 v = W[i];
    __half2 H0 = __floats2half2_rn(v.x, v.y);
    __half2 H1 = __floats2half2_rn(v.z, v.w);
    uint2 u; u.x = *(uint32_t*)&H0; u.y = *(uint32_t*)&H1;
    reinterpret_cast<uint2*>(g_Wh)[i] = u;
}

__global__ void xcvt_kernel(const float4* __restrict__ x, int n4) {
    int i = blockIdx.x * blockDim.x + threadIdx.x;
    if (i >= n4) return;
    float4 v = x[i];
    __half2 H0 = __floats2half2_rn(v.x, v.y);
    __half2 H1 = __floats2half2_rn(v.z, v.w);
    uint2 u; u.x = *(uint32_t*)&H0; u.y = *(uint32_t*)&H1;
    reinterpret_cast<uint2*>(g_xH)[i] = u;
}

// ---------------------------------------------------------------------------
// One layer: C = relu(A @ W + bias)   -- plain fp16 MMA, fp32 accumulate
// ---------------------------------------------------------------------------
__global__ __launch_bounds__(256, 2)
void gemm_relu_kernel(const __half* __restrict__ A,
                      const __half* __restrict__ B,     // layer base [2049][2048] fp16
                      const float* __restrict__ bias,   // fp32 W row 2048
                      float* __restrict__ outF,
                      __half* __restrict__ nextA,
                      int is_last)
{
    extern __shared__ __align__(128) __half smem[];
    const uint32_t sb = (uint32_t)__cvta_generic_to_shared(smem);

    const int tid = threadIdx.x;
    const int lane = tid & 31;
    const int warp = tid >> 5;
    const int warp_m = warp >> 1;   // 0..3 (32 rows each)
    const int warp_n = warp & 1;    // 0..1 (64 cols each)
    const int bm = blockIdx.y;
    const int bn = blockIdx.x;

    const __half* A_base = A + (size_t)(bm * BLK_M) * KDIM;

    // cp.async mapping: 8 x 16B per thread per stage
    const int a_row = tid >> 1;              // 0..127
    const int a_cb  = (tid & 1) * 32;        // col base 0 or 32
    const int b_row = tid >> 4;              // 0..15 (+16,+32,+48)
    const int b_c8  = (tid & 15) * 8;

    auto load_stage = [&](int s, int ko) {
        const uint32_t base = sb + s * STAGE_BYTES;
        {   // A: 128 rows x 64 cols; thread: 1 row, 4 chunks of 8
            const size_t goff = (size_t)a_row * KDIM + ko * BLK_K + a_cb;
            const uint32_t soff = base + (a_row * A_STRIDE + a_cb) * 2;
#pragma unroll
            for (int q = 0; q < 4; q++)
                cp16(soff + q * 16, A_base + goff + q * 8);
        }
        {   // B: 64 rows x 128 cols; thread: 4 rows, 1 chunk each
#pragma unroll
            for (int p = 0; p < 4; p++) {
                const int r = b_row + p * 16;
                const size_t goff = (size_t)(ko * BLK_K + r) * NDIM + bn * BLK_N + b_c8;
                const uint32_t soff = base + (A_TILE + r * B_STRIDE + b_c8) * 2;
                cp16(soff, B + goff);
            }
        }
        CP_COMMIT();
    };

    float acc[2][8][4];
#pragma unroll
    for (int i = 0; i < 2; i++)
#pragma unroll
        for (int j = 0; j < 8; j++)
#pragma unroll
            for (int k = 0; k < 4; k++) acc[i][j][k] = 0.f;

    auto compute_stage = [&](int s) {
        const __half* Ah = smem + s * STAGE_ELEMS;
        const __half* Bh = Ah + A_TILE;
#pragma unroll
        for (int kk = 0; kk < 4; kk++) {
            uint32_t ah[2][4];
#pragma unroll
            for (int mi = 0; mi < 2; mi++) {
                const int aoff = (warp_m * 32 + mi * 16 + (lane & 15)) * A_STRIDE
                               + kk * 16 + ((lane >> 4) << 3);
                ldsm4(ah[mi], Ah + aoff);
            }
#pragma unroll
            for (int ng = 0; ng < 4; ng++) {
                uint32_t bh[4];
                const int boff = (kk * 16 + (lane & 15)) * B_STRIDE
                               + warp_n * 64 + ng * 16 + ((lane >> 4) << 3);
                ldsm4t(bh, Bh + boff);
#pragma unroll
                for (int mi = 0; mi < 2; mi++)
#pragma unroll
                    for (int h = 0; h < 2; h++)
                        mma_f16(acc[mi][ng * 2 + h], ah[mi], &bh[h * 2]);
            }
        }
    };

    // ---------------- 3-stage pipeline ----------------
    load_stage(0, 0);
    load_stage(1, 1);
#pragma unroll 1
    for (int c = 0; c < CHUNKS; c++) {
        CP_WAIT(1);
        __syncthreads();
        compute_stage(c % STAGES);
        if (c + 2 < CHUNKS) load_stage((c + 2) % STAGES, c + 2);
    }

    // ---------------- epilogue: bias + ReLU + store ----------------
    const int row0 = bm * BLK_M + warp_m * 32 + (lane >> 2);
    const int col0 = bn * BLK_N + warp_n * 64 + (lane & 3) * 2;
#pragma unroll
    for (int mi = 0; mi < 2; mi++) {
#pragma unroll
        for (int nn = 0; nn < 8; nn++) {
            const int c = col0 + nn * 8;
            const float b0 = __ldg(bias + c);
            const float b1 = __ldg(bias + c + 1);
            const int r = row0 + mi * 16;
            float v00 = fmaxf(acc[mi][nn][0] + b0, 0.f);
            float v01 = fmaxf(acc[mi][nn][1] + b1, 0.f);
            float v10 = fmaxf(acc[mi][nn][2] + b0, 0.f);
            float v11 = fmaxf(acc[mi][nn][3] + b1, 0.f);
            if (is_last) {
                float2 u0; u0.x = v00; u0.y = v01;
                float2 u1; u1.x = v10; u1.y = v11;
                *reinterpret_cast<float2*>(outF + (size_t)r * NDIM + c) = u0;
                *reinterpret_cast<float2*>(outF + (size_t)(r + 8) * NDIM + c) = u1;
            } else {
                __half2 h0 = __floats2half2_rn(v00, v01);
                __half2 h1 = __floats2half2_rn(v10, v11);
                *reinterpret_cast<__half2*>(nextA + (size_t)r * NDIM + c) = h0;
                *reinterpret_cast<__half2*>(nextA + (size_t)(r + 8) * NDIM + c) = h1;
            }
        }
    }
}

// ---------------------------------------------------------------------------
// launch
// ---------------------------------------------------------------------------
extern "C" void kernel_launch(void* const* d_in, const int* in_sizes, int n_in,
                              void* d_out, int out_size) {
    (void)in_sizes; (void)n_in; (void)out_size;
    const float* x = (const float*)d_in[0];
    const float* W = (const float*)d_in[1];
    float* out = (float*)d_out;

    void *pxh, *pa, *pwh;
    cudaGetSymbolAddress(&pxh, g_xH);
    cudaGetSymbolAddress(&pa, g_a);
    cudaGetSymbolAddress(&pwh, g_Wh);
    __half* xH = (__half*)pxh;
    __half* aP = (__half*)pa;      // [2][B*N]
    __half* Wh = (__half*)pwh;
    const size_t ACT = (size_t)BDIM * NDIM;

    const int w4 = DEPTH * WROWS * NDIM / 4;
    wcvt_kernel<<<(w4 + 255) / 256, 256>>>((const float4*)W, w4);
    const int x4 = BDIM * NDIM / 4;
    xcvt_kernel<<<(x4 + 255) / 256, 256>>>((const float4*)x, x4);

    cudaFuncSetAttribute(gemm_relu_kernel,
                         cudaFuncAttributeMaxDynamicSharedMemorySize, SMEM_BYTES);

    dim3 grid(NDIM / BLK_N, BDIM / BLK_M);   // (16, 32)
    for (int l = 0; l < DEPTH; l++) {
        const __half* Al = (l == 0) ? xH : aP + ((l - 1) & 1) * ACT;
        __half* nA = aP + (l & 1) * ACT;
        const size_t woff = (size_t)l * WROWS * NDIM;
        const float* bias = W + woff + (size_t)KDIM * NDIM;
        gemm_relu_kernel<<<grid, 256, SMEM_BYTES>>>(
            Al, Wh + woff, bias, out, nA,
            (l == DEPTH - 1) ? 1 : 0);
    }
}

// round 8
// speedup vs baseline: 2.9529x; 1.1755x over previous
#include <cuda_runtime.h>
#include <cuda_fp16.h>
#include <cstdint>

// ---------------------------------------------------------------------------
// Problem dims
// ---------------------------------------------------------------------------
#define BDIM 4096
#define NDIM 2048
#define KDIM 2048
#define DEPTH 7
#define WROWS 2049            // K rows + bias row

// ---------------------------------------------------------------------------
// Tiling: 128x128 CTA tile, K-chunks of 64, 3-stage cp.async pipeline
// SMEM uses SW128 XOR swizzle (no padding): conflict-free ldmatrix.
// ---------------------------------------------------------------------------
#define BLK_M 128
#define BLK_N 128
#define BLK_K 64
#define CHUNKS (KDIM / BLK_K)     // 32
#define STAGES 3

// A tile: 128 rows x 64 halves (128B rows)          -> 16384 B
// B tile: 2 subtiles x 64 rows x 64 halves (128B)   -> 16384 B
#define A_BYTES 16384
#define B_SUB_BYTES 8192
#define STAGE_BYTES (A_BYTES + 2 * B_SUB_BYTES)      // 32768
#define SMEM_BYTES (STAGES * STAGE_BYTES)            // 98304 (2 CTAs/SM)

// SW128 swizzle on a relative byte offset (128B rows)
#define SW(x) ((x) ^ (((x) >> 3) & 0x70))

// ---------------------------------------------------------------------------
// Device scratch (allocation-free rule)
// ---------------------------------------------------------------------------
__device__ __half g_xH[(size_t)BDIM * NDIM];              // input, fp16
__device__ __half g_a[2][(size_t)BDIM * NDIM];            // ping-pong activations, fp16
__device__ __half g_Wh[(size_t)DEPTH * WROWS * NDIM];     // weights, fp16

// ---------------------------------------------------------------------------
// helpers
// ---------------------------------------------------------------------------
__device__ __forceinline__ void ldsm4_a(uint32_t (&r)[4], uint32_t addr) {
    asm volatile("ldmatrix.sync.aligned.m8n8.x4.shared.b16 {%0,%1,%2,%3}, [%4];\n"
                 : "=r"(r[0]), "=r"(r[1]), "=r"(r[2]), "=r"(r[3]) : "r"(addr));
}

__device__ __forceinline__ void ldsm4t_a(uint32_t (&r)[4], uint32_t addr) {
    asm volatile("ldmatrix.sync.aligned.m8n8.x4.trans.shared.b16 {%0,%1,%2,%3}, [%4];\n"
                 : "=r"(r[0]), "=r"(r[1]), "=r"(r[2]), "=r"(r[3]) : "r"(addr));
}

__device__ __forceinline__ void mma_f16(float (&d)[4], const uint32_t (&a)[4], const uint32_t* b) {
    asm volatile(
        "mma.sync.aligned.m16n8k16.row.col.f32.f16.f16.f32 "
        "{%0,%1,%2,%3}, {%4,%5,%6,%7}, {%8,%9}, {%0,%1,%2,%3};\n"
        : "+f"(d[0]), "+f"(d[1]), "+f"(d[2]), "+f"(d[3])
        : "r"(a[0]), "r"(a[1]), "r"(a[2]), "r"(a[3]), "r"(b[0]), "r"(b[1]));
}

__device__ __forceinline__ void cp16(uint32_t dst, const void* src) {
    asm volatile("cp.async.cg.shared.global [%0], [%1], 16;" :: "r"(dst), "l"(src));
}
#define CP_COMMIT() asm volatile("cp.async.commit_group;" ::: "memory")
#define CP_WAIT(n)  asm volatile("cp.async.wait_group %0;" :: "n"(n) : "memory")

// ---------------------------------------------------------------------------
// prep kernels: fp32 -> fp16
// ---------------------------------------------------------------------------
__global__ void wcvt_kernel(const float4* __restrict__ W, int n4) {
    int i = blockIdx.x * blockDim.x + threadIdx.x;
    if (i >= n4) return;
    float4 v = W[i];
    __half2 H0 = __floats2half2_rn(v.x, v.y);
    __half2 H1 = __floats2half2_rn(v.z, v.w);
    uint2 u; u.x = *(uint32_t*)&H0; u.y = *(uint32_t*)&H1;
    reinterpret_cast<uint2*>(g_Wh)[i] = u;
}

__global__ void xcvt_kernel(const float4* __restrict__ x, int n4) {
    int i = blockIdx.x * blockDim.x + threadIdx.x;
    if (i >= n4) return;
    float4 v = x[i];
    __half2 H0 = __floats2half2_rn(v.x, v.y);
    __half2 H1 = __floats2half2_rn(v.z, v.w);
    uint2 u; u.x = *(uint32_t*)&H0; u.y = *(uint32_t*)&H1;
    reinterpret_cast<uint2*>(g_xH)[i] = u;
}

// ---------------------------------------------------------------------------
// One layer: C = relu(A @ W + bias)   -- plain fp16 MMA, fp32 accumulate
// ---------------------------------------------------------------------------
__global__ __launch_bounds__(256, 2)
void gemm_relu_kernel(const __half* __restrict__ A,
                      const __half* __restrict__ B,     // layer base [2049][2048] fp16
                      const float* __restrict__ bias,   // fp32 W row 2048
                      float* __restrict__ outF,
                      __half* __restrict__ nextA,
                      int is_last)
{
    extern __shared__ __align__(128) __half smem[];
    const uint32_t sb = (uint32_t)__cvta_generic_to_shared(smem);

    const int tid = threadIdx.x;
    const int lane = tid & 31;
    const int warp = tid >> 5;
    const int warp_m = warp >> 1;   // 0..3 (32 rows each)
    const int warp_n = warp & 1;    // 0..1 (64 cols each -> B subtile)
    const int bm = blockIdx.y;
    const int bn = blockIdx.x;

    const __half* A_base = A + (size_t)(bm * BLK_M) * KDIM;

    // cp.async mapping: 8 x 16B granules per thread per stage
    const int a_row = tid >> 1;              // 0..127
    const int a_gb  = (tid & 1) * 4;         // granule base 0 or 4 (granule = 8 halves)
    const int b_r0  = tid >> 4;              // 0..15 (+16,+32,+48)
    const int b_gc  = tid & 15;              // granule col 0..15 (col = gc*8)

    auto load_stage = [&](int s, int ko) {
        const uint32_t base = (uint32_t)(s * STAGE_BYTES);
        {   // A: 128 rows x 8 granules; thread: 1 row, 4 granules
            const size_t goff = (size_t)a_row * KDIM + ko * BLK_K + a_gb * 8;
            const uint32_t rel0 = base + a_row * 128 + a_gb * 16;
#pragma unroll
            for (int q = 0; q < 4; q++)
                cp16(sb + SW(rel0 + q * 16), A_base + goff + q * 8);
        }
        {   // B: 64 rows x 16 granules; thread: 4 rows, 1 granule each
            const uint32_t bsub = base + A_BYTES + (b_gc >> 3) * B_SUB_BYTES;
            const uint32_t gin = (b_gc & 7) * 16;
#pragma unroll
            for (int p = 0; p < 4; p++) {
                const int r = b_r0 + p * 16;
                const size_t goff = (size_t)(ko * BLK_K + r) * NDIM + bn * BLK_N + b_gc * 8;
                cp16(sb + SW(bsub + r * 128 + gin), B + goff);
            }
        }
        CP_COMMIT();
    };

    float acc[2][8][4];
#pragma unroll
    for (int i = 0; i < 2; i++)
#pragma unroll
        for (int j = 0; j < 8; j++)
#pragma unroll
            for (int k = 0; k < 4; k++) acc[i][j][k] = 0.f;

    auto compute_stage = [&](int s) {
        const uint32_t base = (uint32_t)(s * STAGE_BYTES);
        const uint32_t bsub = base + A_BYTES + warp_n * B_SUB_BYTES;
#pragma unroll
        for (int kk = 0; kk < 4; kk++) {
            uint32_t ah[2][4];
#pragma unroll
            for (int mi = 0; mi < 2; mi++) {
                const int r = warp_m * 32 + mi * 16 + (lane & 15);
                const uint32_t rel = base + r * 128 + (kk * 16 + ((lane >> 4) << 3)) * 2;
                ldsm4_a(ah[mi], sb + SW(rel));
            }
#pragma unroll
            for (int ng = 0; ng < 4; ng++) {
                uint32_t bh[4];
                const int kr = kk * 16 + (lane & 15);
                const uint32_t rel = bsub + kr * 128 + (ng * 16 + ((lane >> 4) << 3)) * 2;
                ldsm4t_a(bh, sb + SW(rel));
#pragma unroll
                for (int mi = 0; mi < 2; mi++)
#pragma unroll
                    for (int h = 0; h < 2; h++)
                        mma_f16(acc[mi][ng * 2 + h], ah[mi], &bh[h * 2]);
            }
        }
    };

    // ---------------- 3-stage pipeline ----------------
    load_stage(0, 0);
    load_stage(1, 1);
#pragma unroll 1
    for (int c = 0; c < CHUNKS; c++) {
        CP_WAIT(1);
        __syncthreads();
        compute_stage(c % STAGES);
        if (c + 2 < CHUNKS) load_stage((c + 2) % STAGES, c + 2);
    }

    // ---------------- epilogue: bias + ReLU + store ----------------
    const int row0 = bm * BLK_M + warp_m * 32 + (lane >> 2);
    const int col0 = bn * BLK_N + warp_n * 64 + (lane & 3) * 2;
#pragma unroll
    for (int mi = 0; mi < 2; mi++) {
#pragma unroll
        for (int nn = 0; nn < 8; nn++) {
            const int c = col0 + nn * 8;
            const float b0 = __ldg(bias + c);
            const float b1 = __ldg(bias + c + 1);
            const int r = row0 + mi * 16;
            float v00 = fmaxf(acc[mi][nn][0] + b0, 0.f);
            float v01 = fmaxf(acc[mi][nn][1] + b1, 0.f);
            float v10 = fmaxf(acc[mi][nn][2] + b0, 0.f);
            float v11 = fmaxf(acc[mi][nn][3] + b1, 0.f);
            if (is_last) {
                float2 u0; u0.x = v00; u0.y = v01;
                float2 u1; u1.x = v10; u1.y = v11;
                *reinterpret_cast<float2*>(outF + (size_t)r * NDIM + c) = u0;
                *reinterpret_cast<float2*>(outF + (size_t)(r + 8) * NDIM + c) = u1;
            } else {
                __half2 h0 = __floats2half2_rn(v00, v01);
                __half2 h1 = __floats2half2_rn(v10, v11);
                *reinterpret_cast<__half2*>(nextA + (size_t)r * NDIM + c) = h0;
                *reinterpret_cast<__half2*>(nextA + (size_t)(r + 8) * NDIM + c) = h1;
            }
        }
    }
}

// ---------------------------------------------------------------------------
// launch
// ---------------------------------------------------------------------------
extern "C" void kernel_launch(void* const* d_in, const int* in_sizes, int n_in,
                              void* d_out, int out_size) {
    (void)in_sizes; (void)n_in; (void)out_size;
    const float* x = (const float*)d_in[0];
    const float* W = (const float*)d_in[1];
    float* out = (float*)d_out;

    void *pxh, *pa, *pwh;
    cudaGetSymbolAddress(&pxh, g_xH);
    cudaGetSymbolAddress(&pa, g_a);
    cudaGetSymbolAddress(&pwh, g_Wh);
    __half* xH = (__half*)pxh;
    __half* aP = (__half*)pa;      // [2][B*N]
    __half* Wh = (__half*)pwh;
    const size_t ACT = (size_t)BDIM * NDIM;

    const int w4 = DEPTH * WROWS * NDIM / 4;
    wcvt_kernel<<<(w4 + 255) / 256, 256>>>((const float4*)W, w4);
    const int x4 = BDIM * NDIM / 4;
    xcvt_kernel<<<(x4 + 255) / 256, 256>>>((const float4*)x, x4);

    cudaFuncSetAttribute(gemm_relu_kernel,
                         cudaFuncAttributeMaxDynamicSharedMemorySize, SMEM_BYTES);

    dim3 grid(NDIM / BLK_N, BDIM / BLK_M);   // (16, 32)
    for (int l = 0; l < DEPTH; l++) {
        const __half* Al = (l == 0) ? xH : aP + ((l - 1) & 1) * ACT;
        __half* nA = aP + (l & 1) * ACT;
        const size_t woff = (size_t)l * WROWS * NDIM;
        const float* bias = W + woff + (size_t)KDIM * NDIM;
        gemm_relu_kernel<<<grid, 256, SMEM_BYTES>>>(
            Al, Wh + woff, bias, out, nA,
            (l == DEPTH - 1) ? 1 : 0);
    }
}

// round 9
// speedup vs baseline: 3.0118x; 1.0200x over previous
#include <cuda_runtime.h>
#include <cuda_fp16.h>
#include <cstdint>

// ---------------------------------------------------------------------------
// Problem dims
// ---------------------------------------------------------------------------
#define BDIM 4096
#define NDIM 2048
#define KDIM 2048
#define DEPTH 7
#define WROWS 2049            // K rows + bias row

// ---------------------------------------------------------------------------
// Tiling: 128x128 CTA tile, K-chunks of 64, 3-stage cp.async pipeline
// SW128 XOR swizzle, addresses hoisted algebraically out of inner loops.
// ---------------------------------------------------------------------------
#define BLK_M 128
#define BLK_N 128
#define BLK_K 64
#define CHUNKS (KDIM / BLK_K)     // 32
#define STAGES 3

#define A_BYTES 16384             // 128 rows x 128B
#define B_SUB_BYTES 8192          // 64 rows x 128B per N-half subtile
#define STAGE_BYTES (A_BYTES + 2 * B_SUB_BYTES)      // 32768
#define SMEM_BYTES (STAGES * STAGE_BYTES)            // 98304 (2 CTAs/SM)

// ---------------------------------------------------------------------------
// Device scratch (allocation-free rule)
// ---------------------------------------------------------------------------
__device__ __half g_xH[(size_t)BDIM * NDIM];
__device__ __half g_a[2][(size_t)BDIM * NDIM];
__device__ __half g_Wh[(size_t)DEPTH * WROWS * NDIM];

// ---------------------------------------------------------------------------
// helpers
// ---------------------------------------------------------------------------
__device__ __forceinline__ void ldsm4_a(uint32_t (&r)[4], uint32_t addr) {
    asm volatile("ldmatrix.sync.aligned.m8n8.x4.shared.b16 {%0,%1,%2,%3}, [%4];\n"
                 : "=r"(r[0]), "=r"(r[1]), "=r"(r[2]), "=r"(r[3]) : "r"(addr));
}

__device__ __forceinline__ void ldsm4t_a(uint32_t (&r)[4], uint32_t addr) {
    asm volatile("ldmatrix.sync.aligned.m8n8.x4.trans.shared.b16 {%0,%1,%2,%3}, [%4];\n"
                 : "=r"(r[0]), "=r"(r[1]), "=r"(r[2]), "=r"(r[3]) : "r"(addr));
}

__device__ __forceinline__ void mma_f16(float (&d)[4], const uint32_t (&a)[4], const uint32_t* b) {
    asm volatile(
        "mma.sync.aligned.m16n8k16.row.col.f32.f16.f16.f32 "
        "{%0,%1,%2,%3}, {%4,%5,%6,%7}, {%8,%9}, {%0,%1,%2,%3};\n"
        : "+f"(d[0]), "+f"(d[1]), "+f"(d[2]), "+f"(d[3])
        : "r"(a[0]), "r"(a[1]), "r"(a[2]), "r"(a[3]), "r"(b[0]), "r"(b[1]));
}

__device__ __forceinline__ void cp16(uint32_t dst, const void* src) {
    asm volatile("cp.async.cg.shared.global [%0], [%1], 16;" :: "r"(dst), "l"(src));
}
#define CP_COMMIT() asm volatile("cp.async.commit_group;" ::: "memory")
#define CP_WAIT(n)  asm volatile("cp.async.wait_group %0;" :: "n"(n) : "memory")

// ---------------------------------------------------------------------------
// prep kernels: fp32 -> fp16
// ---------------------------------------------------------------------------
__global__ void wcvt_kernel(const float4* __restrict__ W, int n4) {
    int i = blockIdx.x * blockDim.x + threadIdx.x;
    if (i >= n4) return;
    float4 v = W[i];
    __half2 H0 = __floats2half2_rn(v.x, v.y);
    __half2 H1 = __floats2half2_rn(v.z, v.w);
    uint2 u; u.x = *(uint32_t*)&H0; u.y = *(uint32_t*)&H1;
    reinterpret_cast<uint2*>(g_Wh)[i] = u;
}

__global__ void xcvt_kernel(const float4* __restrict__ x, int n4) {
    int i = blockIdx.x * blockDim.x + threadIdx.x;
    if (i >= n4) return;
    float4 v = x[i];
    __half2 H0 = __floats2half2_rn(v.x, v.y);
    __half2 H1 = __floats2half2_rn(v.z, v.w);
    uint2 u; u.x = *(uint32_t*)&H0; u.y = *(uint32_t*)&H1;
    reinterpret_cast<uint2*>(g_xH)[i] = u;
}

// ---------------------------------------------------------------------------
// One layer: C = relu(A @ W + bias)   -- fp16 MMA, fp32 accumulate
// ---------------------------------------------------------------------------
__global__ __launch_bounds__(256, 2)
void gemm_relu_kernel(const __half* __restrict__ A,
                      const __half* __restrict__ B,
                      const float* __restrict__ bias,
                      float* __restrict__ outF,
                      __half* __restrict__ nextA,
                      int is_last)
{
    extern __shared__ __align__(128) __half smem[];
    const uint32_t sb = (uint32_t)__cvta_generic_to_shared(smem);

    const int tid = threadIdx.x;
    const int lane = tid & 31;
    const int warp = tid >> 5;
    const int warp_m = warp >> 1;   // 0..3 (32 rows)
    const int warp_n = warp & 1;    // 0..1 (64 cols -> B subtile)
    const int bm = blockIdx.y;
    const int bn = blockIdx.x;

    // ---------------- precomputed cp.async addresses ----------------
    // A: thread -> 1 row, 4 granules of 16B
    const int a_row = tid >> 1;
    const int a_gb16 = (tid & 1) * 64;                 // byte col base: 0 or 64
    const uint32_t a_xor = (uint32_t)((a_row & 7) << 4);
    // swizzled dst (stage-relative): a_row*128 + ((a_gb16 + q*16) ^ a_xor)
    const uint32_t dstA0 = sb + (uint32_t)(a_row * 128) + (uint32_t)(a_gb16 ^ a_xor);
    const __half* gA = A + (size_t)(bm * BLK_M + a_row) * KDIM + (tid & 1) * 32;

    // B: thread -> 4 rows (b_r0 + p*16), 1 granule
    const int b_r0 = tid >> 4;
    const int b_gc = tid & 15;
    const uint32_t b_xor = (uint32_t)((b_r0 & 7) << 4);
    const uint32_t dstB0 = sb + (uint32_t)A_BYTES + (uint32_t)((b_gc >> 3) * B_SUB_BYTES)
                         + (uint32_t)(b_r0 * 128) + ((uint32_t)((b_gc & 7) * 16) ^ b_xor);
    const __half* gB = B + (size_t)b_r0 * NDIM + bn * BLK_N + b_gc * 8;

    auto load_stage = [&](int s, const __half* gA_c, const __half* gB_c) {
        const uint32_t sbase = (uint32_t)(s * STAGE_BYTES);
#pragma unroll
        for (int q = 0; q < 4; q++)
            cp16((dstA0 ^ (uint32_t)(q * 16)) + sbase, gA_c + q * 8);
#pragma unroll
        for (int p = 0; p < 4; p++)
            cp16(dstB0 + sbase + (uint32_t)(p * 2048), gB_c + (size_t)(p * 16) * NDIM);
        CP_COMMIT();
    };

    // ---------------- precomputed ldsm addresses (stage-relative) ----------------
    // A: row r = warp_m*32 + mi*16 + (lane&15); col = kk*32 + ((lane>>4)*16)
    const uint32_t a_hi16 = (uint32_t)(((lane >> 4) << 4));
    uint32_t aAddr[2];
#pragma unroll
    for (int mi = 0; mi < 2; mi++) {
        const int r = warp_m * 32 + mi * 16 + (lane & 15);
        aAddr[mi] = sb + (uint32_t)(r * 128) + (a_hi16 ^ (uint32_t)((r & 7) << 4));
    }
    // B: row = kk*16 + (lane&15); col = ng*32 + ((lane>>4)*16); (row&7)=lane&7
    const uint32_t bAddr0 = sb + (uint32_t)A_BYTES + (uint32_t)(warp_n * B_SUB_BYTES)
                          + (uint32_t)((lane & 15) * 128)
                          + (a_hi16 ^ (uint32_t)((lane & 7) << 4));

    float acc[2][8][4];
#pragma unroll
    for (int i = 0; i < 2; i++)
#pragma unroll
        for (int j = 0; j < 8; j++)
#pragma unroll
            for (int k = 0; k < 4; k++) acc[i][j][k] = 0.f;

    auto compute_stage = [&](int s) {
        const uint32_t sbase = (uint32_t)(s * STAGE_BYTES);
#pragma unroll
        for (int kk = 0; kk < 4; kk++) {
            uint32_t ah[2][4];
#pragma unroll
            for (int mi = 0; mi < 2; mi++)
                ldsm4_a(ah[mi], (aAddr[mi] ^ (uint32_t)(kk << 5)) + sbase);
#pragma unroll
            for (int ng = 0; ng < 4; ng++) {
                uint32_t bh[4];
                ldsm4t_a(bh, (bAddr0 ^ (uint32_t)(ng << 5)) + sbase + (uint32_t)(kk * 2048));
#pragma unroll
                for (int mi = 0; mi < 2; mi++)
#pragma unroll
                    for (int h = 0; h < 2; h++)
                        mma_f16(acc[mi][ng * 2 + h], ah[mi], &bh[h * 2]);
            }
        }
    };

    // ---------------- 3-stage pipeline ----------------
    const __half* gA_c = gA;
    const __half* gB_c = gB;
    load_stage(0, gA_c, gB_c);
    gA_c += BLK_K; gB_c += (size_t)BLK_K * NDIM;
    load_stage(1, gA_c, gB_c);
    gA_c += BLK_K; gB_c += (size_t)BLK_K * NDIM;
#pragma unroll 1
    for (int c = 0; c < CHUNKS; c++) {
        CP_WAIT(1);
        __syncthreads();
        compute_stage(c % STAGES);
        if (c + 2 < CHUNKS) {
            load_stage((c + 2) % STAGES, gA_c, gB_c);
            gA_c += BLK_K; gB_c += (size_t)BLK_K * NDIM;
        }
    }

    // ---------------- epilogue: bias + ReLU + store ----------------
    const int row0 = bm * BLK_M + warp_m * 32 + (lane >> 2);
    const int col0 = bn * BLK_N + warp_n * 64 + (lane & 3) * 2;
#pragma unroll
    for (int mi = 0; mi < 2; mi++) {
#pragma unroll
        for (int nn = 0; nn < 8; nn++) {
            const int c = col0 + nn * 8;
            const float b0 = __ldg(bias + c);
            const float b1 = __ldg(bias + c + 1);
            const int r = row0 + mi * 16;
            float v00 = fmaxf(acc[mi][nn][0] + b0, 0.f);
            float v01 = fmaxf(acc[mi][nn][1] + b1, 0.f);
            float v10 = fmaxf(acc[mi][nn][2] + b0, 0.f);
            float v11 = fmaxf(acc[mi][nn][3] + b1, 0.f);
            if (is_last) {
                float2 u0; u0.x = v00; u0.y = v01;
                float2 u1; u1.x = v10; u1.y = v11;
                *reinterpret_cast<float2*>(outF + (size_t)r * NDIM + c) = u0;
                *reinterpret_cast<float2*>(outF + (size_t)(r + 8) * NDIM + c) = u1;
            } else {
                __half2 h0 = __floats2half2_rn(v00, v01);
                __half2 h1 = __floats2half2_rn(v10, v11);
                *reinterpret_cast<__half2*>(nextA + (size_t)r * NDIM + c) = h0;
                *reinterpret_cast<__half2*>(nextA + (size_t)(r + 8) * NDIM + c) = h1;
            }
        }
    }
}

// ---------------------------------------------------------------------------
// launch
// ---------------------------------------------------------------------------
extern "C" void kernel_launch(void* const* d_in, const int* in_sizes, int n_in,
                              void* d_out, int out_size) {
    (void)in_sizes; (void)n_in; (void)out_size;
    const float* x = (const float*)d_in[0];
    const float* W = (const float*)d_in[1];
    float* out = (float*)d_out;

    void *pxh, *pa, *pwh;
    cudaGetSymbolAddress(&pxh, g_xH);
    cudaGetSymbolAddress(&pa, g_a);
    cudaGetSymbolAddress(&pwh, g_Wh);
    __half* xH = (__half*)pxh;
    __half* aP = (__half*)pa;
    __half* Wh = (__half*)pwh;
    const size_t ACT = (size_t)BDIM * NDIM;

    const int w4 = DEPTH * WROWS * NDIM / 4;
    wcvt_kernel<<<(w4 + 255) / 256, 256>>>((const float4*)W, w4);
    const int x4 = BDIM * NDIM / 4;
    xcvt_kernel<<<(x4 + 255) / 256, 256>>>((const float4*)x, x4);

    cudaFuncSetAttribute(gemm_relu_kernel,
                         cudaFuncAttributeMaxDynamicSharedMemorySize, SMEM_BYTES);

    dim3 grid(NDIM / BLK_N, BDIM / BLK_M);   // (16, 32)
    for (int l = 0; l < DEPTH; l++) {
        const __half* Al = (l == 0) ? xH : aP + ((l - 1) & 1) * ACT;
        __half* nA = aP + (l & 1) * ACT;
        const size_t woff = (size_t)l * WROWS * NDIM;
        const float* bias = W + woff + (size_t)KDIM * NDIM;
        gemm_relu_kernel<<<grid, 256, SMEM_BYTES>>>(
            Al, Wh + woff, bias, out, nA,
            (l == DEPTH - 1) ? 1 : 0);
    }
}